// round 15
// baseline (speedup 1.0000x reference)
#include <cuda_runtime.h>
#include <cuda_bf16.h>
#include <cstdint>

// GraphSAGE on GB300 (sm_103a harness, PTX sm_103 base — no tcgen05).
// R14: latency attack — 768 threads (24 warps): 8 MMA warps (m32n32, as R13)
// + 16 gather warps with 4 nodes each (serial ring steps halved, 2x chip
// MLP). Same math order as R11/R13 -> identical rel_err.

#define N_NODES 100000
#define D 128
#define KNE 16
#define BM 64
#define NTHREADS 768
#define TILES ((N_NODES + BM - 1) / BM)   // 1563
#define GRID 152

// smem byte offsets
#define OFF_W     0                        // [phase][hi|lo] 4 x 32768 = 131072
#define OFF_SELF  131072                   // hi 16384 | lo 16384
#define OFF_AGG   163840                   // 2 x (hi 16384 | lo 16384)
#define OFF_BIAS  229376
#define SMEM_TOTAL 229888

typedef unsigned long long ull;

__device__ float g_h[(size_t)N_NODES * D];
__device__ __align__(16) unsigned char g_wt[131072];   // prepped W image

// ---------------- helpers ----------------
__device__ __forceinline__ uint32_t smem_u32(const void* p) {
    uint32_t a;
    asm("{ .reg .u64 t; cvta.to.shared.u64 t, %1; cvt.u32.u64 %0, t; }" : "=r"(a) : "l"(p));
    return a;
}
__device__ __forceinline__ ull add2(ull a, ull b) {
    ull r; asm("add.rn.f32x2 %0, %1, %2;" : "=l"(r) : "l"(a), "l"(b)); return r;
}
__device__ __forceinline__ void unpack2(ull v, float& lo, float& hi) {
    asm("mov.b64 {%0, %1}, %2;" : "=f"(lo), "=f"(hi) : "l"(v));
}
__device__ __forceinline__ void ldsm4(uint32_t* r, uint32_t addr) {
    asm volatile("ldmatrix.sync.aligned.m8n8.x4.shared.b16 {%0,%1,%2,%3}, [%4];"
        : "=r"(r[0]), "=r"(r[1]), "=r"(r[2]), "=r"(r[3]) : "r"(addr));
}
__device__ __forceinline__ void mma_bf16(float* d, const uint32_t* a, const uint32_t* b) {
    asm volatile("mma.sync.aligned.m16n8k16.row.col.f32.bf16.bf16.f32 "
        "{%0,%1,%2,%3}, {%4,%5,%6,%7}, {%8,%9}, {%0,%1,%2,%3};"
        : "+f"(d[0]), "+f"(d[1]), "+f"(d[2]), "+f"(d[3])
        : "r"(a[0]), "r"(a[1]), "r"(a[2]), "r"(a[3]), "r"(b[0]), "r"(b[1]));
}
#define BAR_SYNC(id, n)   asm volatile("bar.sync %0, %1;"   :: "r"(id), "r"(n) : "memory")
#define BAR_ARRIVE(id, n) asm volatile("bar.arrive %0, %1;" :: "r"(id), "r"(n) : "memory")

// XOR-swizzled byte offset in a [rows][256 B] tile: bits 4-6 ^= row&7.
__device__ __host__ __forceinline__ uint32_t sw_off(int row, int byte_in_row) {
    return (uint32_t)(row * 256 + (byte_in_row ^ ((row & 7) << 4)));
}

__device__ __forceinline__ void split_store4(char* hiB, char* loB, int row, int col, float4 v) {
    __nv_bfloat162 h0 = __floats2bfloat162_rn(v.x, v.y);
    __nv_bfloat162 h1 = __floats2bfloat162_rn(v.z, v.w);
    __nv_bfloat162 l0 = __floats2bfloat162_rn(v.x - __bfloat162float(h0.x),
                                              v.y - __bfloat162float(h0.y));
    __nv_bfloat162 l1 = __floats2bfloat162_rn(v.z - __bfloat162float(h1.x),
                                              v.w - __bfloat162float(h1.y));
    uint32_t o = sw_off(row, col * 2);
    ull hv = (ull)(*(uint32_t*)&h0) | ((ull)(*(uint32_t*)&h1) << 32);
    ull lv = (ull)(*(uint32_t*)&l0) | ((ull)(*(uint32_t*)&l1) << 32);
    *(ull*)(hiB + o) = hv;
    *(ull*)(loB + o) = lv;
}
__device__ __forceinline__ int sel4(int4 v, int e) {
    return (e == 0) ? v.x : (e == 1) ? v.y : (e == 2) ? v.z : v.w;
}

// prep: W [256][128] f32 -> swizzled bf16 hi/lo W^T images per k-phase
__global__ void w_prep(const float* __restrict__ W, unsigned char* __restrict__ wt) {
    int i = blockIdx.x * blockDim.x + threadIdx.x;
    if (i >= 256 * 128) return;
    int k = i >> 7, n = i & 127;
    float x = W[(size_t)k * 128 + n];
    __nv_bfloat16 h = __float2bfloat16_rn(x);
    __nv_bfloat16 l = __float2bfloat16_rn(x - __bfloat162float(h));
    int phase = k >> 7, kk = k & 127;
    uint32_t o = sw_off(n, kk * 2);
    *(__nv_bfloat16*)(wt + phase * 65536 + o) = h;
    *(__nv_bfloat16*)(wt + phase * 65536 + 32768 + o) = l;
}

template <bool RELU>
__global__ void __launch_bounds__(NTHREADS, 1)
sage_layer(const float* __restrict__ h_in,
           const int*   __restrict__ nidx,
           const unsigned char* __restrict__ wt,
           const float* __restrict__ bias,
           float*       __restrict__ out)
{
    extern __shared__ char smem_c[];
    const uint32_t sb = smem_u32(smem_c);
    const int tid  = threadIdx.x;
    const int wid  = tid >> 5;
    const int lane = tid & 31;

    // ---- one-time: W (both phases) + bias into smem ----
    {
        const float4* src = (const float4*)wt;
        float4* dst = (float4*)(smem_c + OFF_W);
        #pragma unroll 4
        for (int i = tid; i < 8192; i += NTHREADS) dst[i] = src[i];
    }
    if (tid < 128) ((float*)(smem_c + OFF_BIAS))[tid] = bias[tid];
    float* bias_s = (float*)(smem_c + OFF_BIAS);
    __syncthreads();

    int it = 0;
    for (int tile = blockIdx.x; tile < TILES; tile += gridDim.x, it++) {
        const int base = tile * BM;
        const int buf  = it & 1;

        if (wid >= 8) {
            // ======= GATHER WARPS (8-23): 4 nodes each -> A_agg[buf] =========
            const int g = wid - 8;                       // nodes g*4 .. g*4+3
            if (it >= 2) BAR_SYNC(4 + buf, NTHREADS);    // agg[buf] free
            char* aggHi = smem_c + OFF_AGG + buf * 32768;
            char* aggLo = aggHi + 16384;

            // 64 indices (4 nodes x 16) -> one int4 in lanes 0..15
            int4 v = make_int4(0, 0, 0, 0);
            {
                const int4* gsrc = (const int4*)(nidx + (size_t)(base + g * 4) * KNE);
                if (lane < 16 && base + g * 4 + (lane >> 2) < N_NODES) v = gsrc[lane];
            }

            ull ax[4], ay[4];
            #pragma unroll
            for (int t = 0; t < 4; t++) { ax[t] = 0; ay[t] = 0; }
            float4 rbuf[2][4];                           // depth-2 ring
            #pragma unroll
            for (int s = 0; s < 2; s++)
                #pragma unroll
                for (int t = 0; t < 4; t++) {
                    int id = __shfl_sync(0xffffffffu, sel4(v, s & 3), t * 4 + (s >> 2));
                    rbuf[s][t] = ((const float4*)(h_in + (size_t)id * D))[lane];
                }
            #pragma unroll
            for (int s = 0; s < 16; s++) {
                const int slot = s & 1;
                #pragma unroll
                for (int t = 0; t < 4; t++) {
                    ulonglong2 p = *(ulonglong2*)&rbuf[slot][t];
                    ax[t] = add2(ax[t], p.x);
                    ay[t] = add2(ay[t], p.y);
                }
                if (s < 14) {
                    const int sn = s + 2;
                    #pragma unroll
                    for (int t = 0; t < 4; t++) {
                        int id = __shfl_sync(0xffffffffu, sel4(v, sn & 3),
                                             t * 4 + (sn >> 2));
                        rbuf[slot][t] = ((const float4*)(h_in + (size_t)id * D))[lane];
                    }
                }
            }
            #pragma unroll
            for (int t = 0; t < 4; t++) {
                float x0, x1, x2, x3;
                unpack2(ax[t], x0, x1); unpack2(ay[t], x2, x3);
                split_store4(aggHi, aggLo, g * 4 + t, lane * 4,
                             make_float4(x0 * 0.0625f, x1 * 0.0625f,
                                         x2 * 0.0625f, x3 * 0.0625f));
            }
            BAR_ARRIVE(2 + buf, NTHREADS);               // agg[buf] produced
        } else {
            // ============ MMA WARPS (0-7): m32n32 each (2r x 4c grid) ========
            const int rowBlk = (wid & 1) * 32;
            const int colBlk = (wid >> 1) * 32;

            // self features -> smem split tile (256 threads)
            {
                char* selfHi = smem_c + OFF_SELF;
                char* selfLo = selfHi + 16384;
                #pragma unroll
                for (int q = 0; q < 8; q++) {
                    int i = tid + q * 256;               // 0..2047
                    int row = i >> 5, c4 = i & 31;
                    if (base + row < N_NODES) {
                        float4 vv = ((const float4*)(h_in + (size_t)(base + row) * D))[c4];
                        split_store4(selfHi, selfLo, row, c4 * 4, vv);
                    }
                }
            }
            BAR_SYNC(1, 256);                            // self ready (MMA-only)

            float acc[8][4];
            #pragma unroll
            for (int a = 0; a < 8; a++)
                #pragma unroll
                for (int j = 0; j < 4; j++) acc[a][j] = 0.0f;

            const uint32_t wBase = sb + OFF_W;
            const int akoff = (lane >> 4) * 16;
            const int arow0 = rowBlk + (lane & 15);
            const int brow  = colBlk + ((lane >> 4) & 1) * 8 + (lane & 7);
            const int bkoff = ((lane >> 3) & 1) * 16;

            auto mma_phase = [&](uint32_t aTile, uint32_t wHi) {
                const uint32_t aHi = aTile, aLo = aTile + 16384;
                const uint32_t wLo = wHi + 32768;
                #pragma unroll
                for (int kc = 0; kc < 8; kc++) {
                    const int kb = kc * 32;
                    uint32_t ahr[2][4], alr[2][4];
                    #pragma unroll
                    for (int mi = 0; mi < 2; mi++) {
                        uint32_t ao = sw_off(arow0 + mi * 16, kb + akoff);
                        ldsm4(ahr[mi], aHi + ao);
                        ldsm4(alr[mi], aLo + ao);
                    }
                    #pragma unroll
                    for (int np = 0; np < 2; np++) {     // load-then-use per np
                        uint32_t bh[4], bl[4];
                        uint32_t bo = sw_off(brow + np * 16, kb + bkoff);
                        ldsm4(bh, wHi + bo);
                        ldsm4(bl, wLo + bo);
                        #pragma unroll
                        for (int mi = 0; mi < 2; mi++) {
                            float* a0 = acc[mi * 4 + np * 2];
                            float* a1 = acc[mi * 4 + np * 2 + 1];
                            mma_bf16(a0, ahr[mi], bh);
                            mma_bf16(a0, ahr[mi], bl);
                            mma_bf16(a0, alr[mi], bh);
                            mma_bf16(a1, ahr[mi], bh + 2);
                            mma_bf16(a1, ahr[mi], bl + 2);
                            mma_bf16(a1, alr[mi], bh + 2);
                        }
                    }
                }
            };

            mma_phase(sb + OFF_SELF, wBase);             // phase 1 (self, W0)
            BAR_SYNC(1, 256);
            BAR_SYNC(2 + buf, NTHREADS);                 // agg[buf] produced
            mma_phase(sb + OFF_AGG + buf * 32768, wBase + 65536);  // phase 2
            BAR_ARRIVE(4 + buf, NTHREADS);               // agg[buf] consumed

            // epilogue
            const int qrow = rowBlk + (lane >> 2);
            const int c0 = (lane & 3) * 2;
            #pragma unroll
            for (int mi = 0; mi < 2; mi++)
                #pragma unroll
                for (int half = 0; half < 2; half++) {
                    int r = base + qrow + mi * 16 + half * 8;
                    if (r < N_NODES) {
                        float* orow = out + (size_t)r * D + colBlk + c0;
                        #pragma unroll
                        for (int nt = 0; nt < 4; nt++) {
                            float v0 = acc[mi * 4 + nt][half * 2]
                                     + bias_s[colBlk + nt * 8 + c0];
                            float v1 = acc[mi * 4 + nt][half * 2 + 1]
                                     + bias_s[colBlk + nt * 8 + c0 + 1];
                            if (RELU) { v0 = fmaxf(v0, 0.0f); v1 = fmaxf(v1, 0.0f); }
                            *(float2*)(orow + nt * 8) = make_float2(v0, v1);
                        }
                    }
                }
        }
    }
}

extern "C" void kernel_launch(void* const* d_in, const int* in_sizes, int n_in,
                              void* d_out, int out_size) {
    const float* feats = (const float*)d_in[0];
    const int*   nidx  = (const int*)d_in[1];
    const float* Ws    = (const float*)d_in[2];
    const float* bs    = (const float*)d_in[3];
    float*       out   = (float*)d_out;

    void* p = nullptr;
    cudaGetSymbolAddress(&p, g_h);  float* h1 = (float*)p;
    cudaGetSymbolAddress(&p, g_wt); unsigned char* wt = (unsigned char*)p;

    cudaFuncSetAttribute(sage_layer<true>,  cudaFuncAttributeMaxDynamicSharedMemorySize, SMEM_TOTAL);
    cudaFuncSetAttribute(sage_layer<false>, cudaFuncAttributeMaxDynamicSharedMemorySize, SMEM_TOTAL);

    // layer 0
    w_prep<<<64, 512>>>(Ws, wt);
    sage_layer<true><<<GRID, NTHREADS, SMEM_TOTAL>>>(feats, nidx, wt, bs, h1);
    // layer 1
    w_prep<<<64, 512>>>(Ws + 256 * 128, wt);
    sage_layer<false><<<GRID, NTHREADS, SMEM_TOTAL>>>(
        h1, nidx + (size_t)N_NODES * KNE, wt, bs + 128, out);
}

// round 16
// speedup vs baseline: 1.0747x; 1.0747x over previous
#include <cuda_runtime.h>
#include <cuda_bf16.h>
#include <cstdint>

// GraphSAGE on GB300 (sm_103a harness, PTX sm_103 base — no tcgen05).
// R15 = R13 base (f32 gather, resident W both phases, cross-tile pipeline,
// m32n32 MMA grid) with: MMA warps moved to HIGH wids (8-15; arbiter is
// hi-wid-first per SMSP), A-fragment ping-pong prefetch in the kc loop,
// and __stcs on the final (layer-1) output stores.

#define N_NODES 100000
#define D 128
#define KNE 16
#define BM 64
#define NTHREADS 512
#define TILES ((N_NODES + BM - 1) / BM)   // 1563
#define GRID 152

// smem byte offsets
#define OFF_W     0                        // [phase][hi|lo] 4 x 32768 = 131072
#define OFF_SELF  131072                   // hi 16384 | lo 16384
#define OFF_AGG   163840                   // 2 x (hi 16384 | lo 16384)
#define OFF_BIAS  229376
#define SMEM_TOTAL 229888

typedef unsigned long long ull;

__device__ float g_h[(size_t)N_NODES * D];
__device__ __align__(16) unsigned char g_wt[131072];   // prepped W image

// ---------------- helpers ----------------
__device__ __forceinline__ uint32_t smem_u32(const void* p) {
    uint32_t a;
    asm("{ .reg .u64 t; cvta.to.shared.u64 t, %1; cvt.u32.u64 %0, t; }" : "=r"(a) : "l"(p));
    return a;
}
__device__ __forceinline__ ull add2(ull a, ull b) {
    ull r; asm("add.rn.f32x2 %0, %1, %2;" : "=l"(r) : "l"(a), "l"(b)); return r;
}
__device__ __forceinline__ void unpack2(ull v, float& lo, float& hi) {
    asm("mov.b64 {%0, %1}, %2;" : "=f"(lo), "=f"(hi) : "l"(v));
}
__device__ __forceinline__ void ldsm4(uint32_t* r, uint32_t addr) {
    asm volatile("ldmatrix.sync.aligned.m8n8.x4.shared.b16 {%0,%1,%2,%3}, [%4];"
        : "=r"(r[0]), "=r"(r[1]), "=r"(r[2]), "=r"(r[3]) : "r"(addr));
}
__device__ __forceinline__ void mma_bf16(float* d, const uint32_t* a, const uint32_t* b) {
    asm volatile("mma.sync.aligned.m16n8k16.row.col.f32.bf16.bf16.f32 "
        "{%0,%1,%2,%3}, {%4,%5,%6,%7}, {%8,%9}, {%0,%1,%2,%3};"
        : "+f"(d[0]), "+f"(d[1]), "+f"(d[2]), "+f"(d[3])
        : "r"(a[0]), "r"(a[1]), "r"(a[2]), "r"(a[3]), "r"(b[0]), "r"(b[1]));
}
#define BAR_SYNC(id, n)   asm volatile("bar.sync %0, %1;"   :: "r"(id), "r"(n) : "memory")
#define BAR_ARRIVE(id, n) asm volatile("bar.arrive %0, %1;" :: "r"(id), "r"(n) : "memory")

// XOR-swizzled byte offset in a [rows][256 B] tile: bits 4-6 ^= row&7.
__device__ __host__ __forceinline__ uint32_t sw_off(int row, int byte_in_row) {
    return (uint32_t)(row * 256 + (byte_in_row ^ ((row & 7) << 4)));
}

__device__ __forceinline__ void split_store4(char* hiB, char* loB, int row, int col, float4 v) {
    __nv_bfloat162 h0 = __floats2bfloat162_rn(v.x, v.y);
    __nv_bfloat162 h1 = __floats2bfloat162_rn(v.z, v.w);
    __nv_bfloat162 l0 = __floats2bfloat162_rn(v.x - __bfloat162float(h0.x),
                                              v.y - __bfloat162float(h0.y));
    __nv_bfloat162 l1 = __floats2bfloat162_rn(v.z - __bfloat162float(h1.x),
                                              v.w - __bfloat162float(h1.y));
    uint32_t o = sw_off(row, col * 2);
    ull hv = (ull)(*(uint32_t*)&h0) | ((ull)(*(uint32_t*)&h1) << 32);
    ull lv = (ull)(*(uint32_t*)&l0) | ((ull)(*(uint32_t*)&l1) << 32);
    *(ull*)(hiB + o) = hv;
    *(ull*)(loB + o) = lv;
}

// prep: W [256][128] f32 -> swizzled bf16 hi/lo W^T images per k-phase
__global__ void w_prep(const float* __restrict__ W, unsigned char* __restrict__ wt) {
    int i = blockIdx.x * blockDim.x + threadIdx.x;
    if (i >= 256 * 128) return;
    int k = i >> 7, n = i & 127;
    float x = W[(size_t)k * 128 + n];
    __nv_bfloat16 h = __float2bfloat16_rn(x);
    __nv_bfloat16 l = __float2bfloat16_rn(x - __bfloat162float(h));
    int phase = k >> 7, kk = k & 127;
    uint32_t o = sw_off(n, kk * 2);
    *(__nv_bfloat16*)(wt + phase * 65536 + o) = h;
    *(__nv_bfloat16*)(wt + phase * 65536 + 32768 + o) = l;
}

template <bool RELU>
__global__ void __launch_bounds__(NTHREADS, 1)
sage_layer(const float* __restrict__ h_in,
           const int*   __restrict__ nidx,
           const unsigned char* __restrict__ wt,
           const float* __restrict__ bias,
           float*       __restrict__ out)
{
    extern __shared__ char smem_c[];
    const uint32_t sb = smem_u32(smem_c);
    const int tid  = threadIdx.x;
    const int wid  = tid >> 5;
    const int lane = tid & 31;

    // ---- one-time: W (both phases) + bias into smem ----
    {
        const float4* src = (const float4*)wt;
        float4* dst = (float4*)(smem_c + OFF_W);
        #pragma unroll 4
        for (int i = tid; i < 8192; i += NTHREADS) dst[i] = src[i];
    }
    if (tid < 128) ((float*)(smem_c + OFF_BIAS))[tid] = bias[tid];
    float* bias_s = (float*)(smem_c + OFF_BIAS);
    __syncthreads();

    int it = 0;
    for (int tile = blockIdx.x; tile < TILES; tile += gridDim.x, it++) {
        const int base = tile * BM;
        const int buf  = it & 1;

        if (wid < 8) {
            // ============ GATHER WARPS (0-7, LOW priority): A_agg[buf] =======
            const int g = wid;                           // nodes g*8 .. g*8+7
            if (it >= 2) BAR_SYNC(4 + buf, 512);         // agg[buf] free
            char* aggHi = smem_c + OFF_AGG + buf * 32768;
            char* aggLo = aggHi + 16384;
            #pragma unroll
            for (int grp = 0; grp < 2; grp++) {
                const int n0g = g * 8 + grp * 4;         // local node base
                const int* gsrc = nidx + (size_t)(base + n0g) * KNE;
                int v0 = 0, v1 = 0;
                if (base + n0g + (lane >> 4) < N_NODES)     v0 = gsrc[lane];
                if (base + n0g + 2 + (lane >> 4) < N_NODES) v1 = gsrc[32 + lane];

                ull ax[4], ay[4];
                #pragma unroll
                for (int t = 0; t < 4; t++) { ax[t] = 0; ay[t] = 0; }
                float4 rbuf[2][4];
                #pragma unroll
                for (int s = 0; s < 2; s++)
                    #pragma unroll
                    for (int t = 0; t < 4; t++) {
                        const int f = t * 16 + s;
                        int id = __shfl_sync(0xffffffffu, (f < 32) ? v0 : v1, f & 31);
                        rbuf[s][t] = ((const float4*)(h_in + (size_t)id * D))[lane];
                    }
                #pragma unroll
                for (int s = 0; s < 16; s++) {
                    const int slot = s & 1;
                    #pragma unroll
                    for (int t = 0; t < 4; t++) {
                        ulonglong2 p = *(ulonglong2*)&rbuf[slot][t];
                        ax[t] = add2(ax[t], p.x);
                        ay[t] = add2(ay[t], p.y);
                    }
                    if (s < 14) {
                        #pragma unroll
                        for (int t = 0; t < 4; t++) {
                            const int f = t * 16 + s + 2;
                            int id = __shfl_sync(0xffffffffu, (f < 32) ? v0 : v1, f & 31);
                            rbuf[slot][t] =
                                ((const float4*)(h_in + (size_t)id * D))[lane];
                        }
                    }
                }
                #pragma unroll
                for (int t = 0; t < 4; t++) {
                    float x0, x1, x2, x3;
                    unpack2(ax[t], x0, x1); unpack2(ay[t], x2, x3);
                    split_store4(aggHi, aggLo, n0g + t, lane * 4,
                                 make_float4(x0 * 0.0625f, x1 * 0.0625f,
                                             x2 * 0.0625f, x3 * 0.0625f));
                }
            }
            BAR_ARRIVE(2 + buf, 512);                    // agg[buf] produced
        } else {
            // ===== MMA WARPS (8-15, HIGH priority): m32n32 (2r x 4c grid) ====
            const int w = wid - 8;
            const int rowBlk = (w & 1) * 32;
            const int colBlk = (w >> 1) * 32;
            const int mtid = tid - 256;                  // 0..255

            // self features -> smem split tile
            {
                char* selfHi = smem_c + OFF_SELF;
                char* selfLo = selfHi + 16384;
                #pragma unroll
                for (int q = 0; q < 8; q++) {
                    int i = mtid + q * 256;              // 0..2047
                    int row = i >> 5, c4 = i & 31;
                    if (base + row < N_NODES) {
                        float4 vv = ((const float4*)(h_in + (size_t)(base + row) * D))[c4];
                        split_store4(selfHi, selfLo, row, c4 * 4, vv);
                    }
                }
            }
            BAR_SYNC(1, 256);                            // self ready (MMA-only)

            float acc[8][4];
            #pragma unroll
            for (int a = 0; a < 8; a++)
                #pragma unroll
                for (int j = 0; j < 4; j++) acc[a][j] = 0.0f;

            const uint32_t wBase = sb + OFF_W;
            const int akoff = (lane >> 4) * 16;
            const int arow0 = rowBlk + (lane & 15);
            const int brow  = colBlk + ((lane >> 4) & 1) * 8 + (lane & 7);
            const int bkoff = ((lane >> 3) & 1) * 16;

            auto mma_phase = [&](uint32_t aTile, uint32_t wHi) {
                const uint32_t aHi = aTile, aLo = aTile + 16384;
                const uint32_t wLo = wHi + 32768;
                uint32_t ahr[2][2][4], alr[2][2][4];     // [ping-pong][mi][frag]
                #pragma unroll
                for (int mi = 0; mi < 2; mi++) {         // preload kc=0
                    uint32_t ao = sw_off(arow0 + mi * 16, akoff);
                    ldsm4(ahr[0][mi], aHi + ao);
                    ldsm4(alr[0][mi], aLo + ao);
                }
                #pragma unroll
                for (int kc = 0; kc < 8; kc++) {
                    const int cur = kc & 1, nxt = cur ^ 1;
                    if (kc < 7) {                        // prefetch A(kc+1)
                        const int kbn = (kc + 1) * 32;
                        #pragma unroll
                        for (int mi = 0; mi < 2; mi++) {
                            uint32_t ao = sw_off(arow0 + mi * 16, kbn + akoff);
                            ldsm4(ahr[nxt][mi], aHi + ao);
                            ldsm4(alr[nxt][mi], aLo + ao);
                        }
                    }
                    const int kb = kc * 32;
                    #pragma unroll
                    for (int np = 0; np < 2; np++) {     // load-then-use per np
                        uint32_t bh[4], bl[4];
                        uint32_t bo = sw_off(brow + np * 16, kb + bkoff);
                        ldsm4(bh, wHi + bo);
                        ldsm4(bl, wLo + bo);
                        #pragma unroll
                        for (int mi = 0; mi < 2; mi++) {
                            float* a0 = acc[mi * 4 + np * 2];
                            float* a1 = acc[mi * 4 + np * 2 + 1];
                            mma_bf16(a0, ahr[cur][mi], bh);
                            mma_bf16(a0, ahr[cur][mi], bl);
                            mma_bf16(a0, alr[cur][mi], bh);
                            mma_bf16(a1, ahr[cur][mi], bh + 2);
                            mma_bf16(a1, ahr[cur][mi], bl + 2);
                            mma_bf16(a1, alr[cur][mi], bh + 2);
                        }
                    }
                }
            };

            mma_phase(sb + OFF_SELF, wBase);             // phase 1 (self, W0)
            BAR_SYNC(1, 256);
            BAR_SYNC(2 + buf, 512);                      // agg[buf] produced
            mma_phase(sb + OFF_AGG + buf * 32768, wBase + 65536);  // phase 2
            BAR_ARRIVE(4 + buf, 512);                    // agg[buf] consumed

            // epilogue
            const int qrow = rowBlk + (lane >> 2);
            const int c0 = (lane & 3) * 2;
            #pragma unroll
            for (int mi = 0; mi < 2; mi++)
                #pragma unroll
                for (int half = 0; half < 2; half++) {
                    int r = base + qrow + mi * 16 + half * 8;
                    if (r < N_NODES) {
                        float* orow = out + (size_t)r * D + colBlk + c0;
                        #pragma unroll
                        for (int nt = 0; nt < 4; nt++) {
                            float v0 = acc[mi * 4 + nt][half * 2]
                                     + bias_s[colBlk + nt * 8 + c0];
                            float v1 = acc[mi * 4 + nt][half * 2 + 1]
                                     + bias_s[colBlk + nt * 8 + c0 + 1];
                            if (RELU) {
                                v0 = fmaxf(v0, 0.0f); v1 = fmaxf(v1, 0.0f);
                                *(float2*)(orow + nt * 8) = make_float2(v0, v1);
                            } else {
                                // final output: never re-read -> streaming store
                                __stcs((float2*)(orow + nt * 8), make_float2(v0, v1));
                            }
                        }
                    }
                }
        }
    }
}

extern "C" void kernel_launch(void* const* d_in, const int* in_sizes, int n_in,
                              void* d_out, int out_size) {
    const float* feats = (const float*)d_in[0];
    const int*   nidx  = (const int*)d_in[1];
    const float* Ws    = (const float*)d_in[2];
    const float* bs    = (const float*)d_in[3];
    float*       out   = (float*)d_out;

    void* p = nullptr;
    cudaGetSymbolAddress(&p, g_h);  float* h1 = (float*)p;
    cudaGetSymbolAddress(&p, g_wt); unsigned char* wt = (unsigned char*)p;

    cudaFuncSetAttribute(sage_layer<true>,  cudaFuncAttributeMaxDynamicSharedMemorySize, SMEM_TOTAL);
    cudaFuncSetAttribute(sage_layer<false>, cudaFuncAttributeMaxDynamicSharedMemorySize, SMEM_TOTAL);

    // layer 0
    w_prep<<<64, 512>>>(Ws, wt);
    sage_layer<true><<<GRID, NTHREADS, SMEM_TOTAL>>>(feats, nidx, wt, bs, h1);
    // layer 1
    w_prep<<<64, 512>>>(Ws + 256 * 128, wt);
    sage_layer<false><<<GRID, NTHREADS, SMEM_TOTAL>>>(
        h1, nidx + (size_t)N_NODES * KNE, wt, bs + 128, out);
}